// round 7
// baseline (speedup 1.0000x reference)
#include <cuda_runtime.h>
#include <cuda_bf16.h>

#define NPART 6144
#define PPAIRS 18871296            // N*(N-1)/2 (fits int32)
#define DISC0_I 150970369          // (2N-1)^2
#define OFF_D (3 * PPAIRS)
#define OFF_B (4 * PPAIRS)
#define OFF_C (5 * PPAIRS)

__device__ __forceinline__ int row_offset(int i) {
    return (i * (2 * NPART - 1 - i)) >> 1;
}

__device__ __forceinline__ float wrap_min_image(float d) {
    // equals jnp.remainder(d + 3, 6) - 3 for d in (-6, 6)
    float t = d + 3.0f;
    if (t < 0.0f)       t += 6.0f;
    else if (t >= 6.0f) t -= 6.0f;
    return t - 3.0f;
}

__device__ __forceinline__ void classify(float dx, float dy, float dz,
                                         float& d, float& bm, float& cm) {
    d  = sqrtf(dx * dx + dy * dy + dz * dz);
    bm = (d < 0.6f)  ? 1.0f : 0.0f;   // in_build (cutoff + skin)
    cm = (d <= 0.5f) ? 1.0f : 0.0f;   // in_cutoff
}

__device__ __forceinline__ void invert_p(int p, int& i, int& j) {
    i = (int)((12287.0f - sqrtf((float)(DISC0_I - 8 * p))) * 0.5f);
    i = max(0, min(NPART - 2, i));
    while (row_offset(i) > p) --i;
    while (row_offset(i + 1) <= p) ++i;
    j = p - row_offset(i) + i + 1;
}

__device__ __forceinline__ void store4(float* __restrict__ out, int p,
                                       const float* dx, const float* dy, const float* dz,
                                       const float* d, const float* bm, const float* cm) {
    float4* r4 = reinterpret_cast<float4*>(out + 3 * p);   // p % 4 == 0
    __stcs(r4 + 0, make_float4(dx[0], dy[0], dz[0], dx[1]));
    __stcs(r4 + 1, make_float4(dy[1], dz[1], dx[2], dy[2]));
    __stcs(r4 + 2, make_float4(dz[2], dx[3], dy[3], dz[3]));
    __stcs(reinterpret_cast<float4*>(out + OFF_D + p), make_float4(d[0],  d[1],  d[2],  d[3]));
    __stcs(reinterpret_cast<float4*>(out + OFF_B + p), make_float4(bm[0], bm[1], bm[2], bm[3]));
    __stcs(reinterpret_cast<float4*>(out + OFF_C + p), make_float4(cm[0], cm[1], cm[2], cm[3]));
}

// Process 128 pairs: p in [p0, p0+128), j = (p - p0) + jA + DELTA.
// Loads are 16B-aligned at jA (jA % 4 == 0); results shifted by DELTA lanes->slots.
template <int DELTA>
__device__ __forceinline__ void do_half(const float* __restrict__ pos,
                                        float* __restrict__ out,
                                        int jA, int p0, int lane,
                                        float rix, float riy, float riz) {
    const float4* g4 = reinterpret_cast<const float4*>(pos + 3 * jA) + 3 * lane;
    const float4 a = __ldg(g4);
    const float4 b = __ldg(g4 + 1);
    const float4 c = __ldg(g4 + 2);

    float dx[4], dy[4], dz[4];
    dx[0] = wrap_min_image(rix - a.x); dy[0] = wrap_min_image(riy - a.y); dz[0] = wrap_min_image(riz - a.z);
    dx[1] = wrap_min_image(rix - a.w); dy[1] = wrap_min_image(riy - b.x); dz[1] = wrap_min_image(riz - b.y);
    dx[2] = wrap_min_image(rix - b.z); dy[2] = wrap_min_image(riy - b.w); dz[2] = wrap_min_image(riz - c.x);
    dx[3] = wrap_min_image(rix - c.y); dy[3] = wrap_min_image(riy - c.z); dz[3] = wrap_min_image(riz - c.w);

    float sx[4], sy[4], sz[4];
    if (DELTA == 0) {
#pragma unroll
        for (int k = 0; k < 4; ++k) { sx[k] = dx[k]; sy[k] = dy[k]; sz[k] = dz[k]; }
    } else {
        float nx[DELTA ? DELTA : 1], ny[DELTA ? DELTA : 1], nz[DELTA ? DELTA : 1];
#pragma unroll
        for (int m = 0; m < DELTA; ++m) {
            // lane 31's missing tail pair comes from j = jA + 128 + m (in-bounds: < p0-row end)
            float exx = 0.f, exy = 0.f, exz = 0.f;
            if (lane == 31) {
                const float* q = pos + 3 * (jA + 128 + m);
                exx = wrap_min_image(rix - __ldg(q));
                exy = wrap_min_image(riy - __ldg(q + 1));
                exz = wrap_min_image(riz - __ldg(q + 2));
            }
            nx[m] = __shfl_sync(0xffffffffu, dx[m], (lane + 1) & 31);
            ny[m] = __shfl_sync(0xffffffffu, dy[m], (lane + 1) & 31);
            nz[m] = __shfl_sync(0xffffffffu, dz[m], (lane + 1) & 31);
            if (lane == 31) { nx[m] = exx; ny[m] = exy; nz[m] = exz; }
        }
#pragma unroll
        for (int k = 0; k < 4; ++k) {
            if (k + DELTA < 4) { sx[k] = dx[k + DELTA]; sy[k] = dy[k + DELTA]; sz[k] = dz[k + DELTA]; }
            else               { sx[k] = nx[k + DELTA - 4]; sy[k] = ny[k + DELTA - 4]; sz[k] = nz[k + DELTA - 4]; }
        }
    }

    float d[4], bm[4], cm[4];
#pragma unroll
    for (int k = 0; k < 4; ++k) classify(sx[k], sy[k], sz[k], d[k], bm[k], cm[k]);

    store4(out, p0 + 4 * lane, sx, sy, sz, d, bm, cm);
}

__global__ __launch_bounds__(128)
void nlist_v6_kernel(const float* __restrict__ pos, float* __restrict__ out) {
    const int tid  = threadIdx.x;
    const int lane = tid & 31;
    const int w    = tid >> 5;

    const int p0w = (blockIdx.x * 4 + w) * 256;

    int iw, jw;
    invert_p(p0w, iw, jw);
    const bool fast = (row_offset(iw + 1) > p0w + 255);   // all 256 pairs in row iw

    if (fast) {
        const float rix = __ldg(pos + 3 * iw);
        const float riy = __ldg(pos + 3 * iw + 1);
        const float riz = __ldg(pos + 3 * iw + 2);
        const int   dlt = jw & 3;            // same for both halves (128 % 4 == 0)
        const int   jA0 = jw - dlt;

        switch (dlt) {
        case 0:
            do_half<0>(pos, out, jA0,       p0w,       lane, rix, riy, riz);
            do_half<0>(pos, out, jA0 + 128, p0w + 128, lane, rix, riy, riz);
            break;
        case 1:
            do_half<1>(pos, out, jA0,       p0w,       lane, rix, riy, riz);
            do_half<1>(pos, out, jA0 + 128, p0w + 128, lane, rix, riy, riz);
            break;
        case 2:
            do_half<2>(pos, out, jA0,       p0w,       lane, rix, riy, riz);
            do_half<2>(pos, out, jA0 + 128, p0w + 128, lane, rix, riy, riz);
            break;
        default:
            do_half<3>(pos, out, jA0,       p0w,       lane, rix, riy, riz);
            do_half<3>(pos, out, jA0 + 128, p0w + 128, lane, rix, riy, riz);
            break;
        }
    } else {
        // slow path: warp straddles a row boundary (rare)
        float dx[4], dy[4], dz[4], d[4], bm[4], cm[4];
#pragma unroll
        for (int half = 0; half < 2; ++half) {
            int p = p0w + 128 * half + 4 * lane;
            int i, j;
            invert_p(p, i, j);
            float rix = __ldg(pos + 3 * i);
            float riy = __ldg(pos + 3 * i + 1);
            float riz = __ldg(pos + 3 * i + 2);
#pragma unroll
            for (int k = 0; k < 4; ++k) {
                const float rjx = __ldg(pos + 3 * j);
                const float rjy = __ldg(pos + 3 * j + 1);
                const float rjz = __ldg(pos + 3 * j + 2);
                dx[k] = wrap_min_image(rix - rjx);
                dy[k] = wrap_min_image(riy - rjy);
                dz[k] = wrap_min_image(riz - rjz);
                classify(dx[k], dy[k], dz[k], d[k], bm[k], cm[k]);
                if (++j == NPART) {
                    ++i; j = i + 1;
                    rix = __ldg(pos + 3 * i);
                    riy = __ldg(pos + 3 * i + 1);
                    riz = __ldg(pos + 3 * i + 2);
                }
            }
            store4(out, p, dx, dy, dz, d, bm, cm);
        }
    }
}

extern "C" void kernel_launch(void* const* d_in, const int* in_sizes, int n_in,
                              void* d_out, int out_size) {
    const float* pos = (const float*)d_in[0];   // positions [N,3] float32
    // d_in[1] = box_vectors (diag 6.0) — compile-time constant
    float* out = (float*)d_out;

    // 73,716 warps * 256 pairs = PPAIRS exactly
    nlist_v6_kernel<<<18429, 128>>>(pos, out);
}